// round 14
// baseline (speedup 1.0000x reference)
#include <cuda_runtime.h>
#include <math.h>

#define LOG100 4.605170185988092f

// B=32, H=W=64, C=60, NH=6, HD=10, WS=7, T=49; 3200 windows, 1/CTA, 320 thr.
// 3 CTAs/SM. Weights pre-transposed into __device__ scratch (line-dense LDG).
// Attention: 2 rows/thread, head-per-warp (single K/V broadcast stream/warp).
// Q: [6][49][12] (stride 12). KV: [6][49][20] = k0..k9|v0..v9.

__device__ float g_qkv_wt[10800];
__device__ float g_proj_wt[3600];

__device__ __forceinline__ unsigned long long pack2(float a, float b) {
    unsigned long long r;
    asm("mov.b64 %0, {%1, %2};" : "=l"(r) : "f"(a), "f"(b));
    return r;
}
__device__ __forceinline__ void unpack2(unsigned long long v, float& a, float& b) {
    asm("mov.b64 {%0, %1}, %2;" : "=f"(a), "=f"(b) : "l"(v));
}
__device__ __forceinline__ unsigned long long fma2(unsigned long long a,
                                                   unsigned long long b,
                                                   unsigned long long c) {
    unsigned long long r;
    asm("fma.rn.f32x2 %0, %1, %2, %3;" : "=l"(r) : "l"(a), "l"(b), "l"(c));
    return r;
}
__device__ __forceinline__ unsigned long long mul2(unsigned long long a,
                                                   unsigned long long b) {
    unsigned long long r;
    asm("mul.rn.f32x2 %0, %1, %2;" : "=l"(r) : "l"(a), "l"(b));
    return r;
}

__global__ void transpose_weights_kernel(const float* __restrict__ qkv_w,
                                         const float* __restrict__ proj_w) {
    int i = blockIdx.x * 256 + threadIdx.x;
    if (i < 10800) {
        int o = i / 60, c = i % 60;
        int c4 = c >> 2, d = c & 3, og = o >> 2, j = o & 3;
        g_qkv_wt[((c4 * 45 + og) * 4 + j) * 4 + d] = qkv_w[i];
    }
    if (i < 3600) {
        int o = i / 60, c = i % 60;
        int c4 = c >> 2, d = c & 3, jg = o >> 1, j = o & 1;
        g_proj_wt[((c4 * 30 + jg) * 2 + j) * 4 + d] = proj_w[i];
    }
}

__global__ __launch_bounds__(320, 3) void swin_win_attn_kernel(
    const float* __restrict__ x,       // [32,64,64,60]
    const float* __restrict__ qkv_b,   // [180]
    const float* __restrict__ ls,      // [6]
    const float* __restrict__ proj_b,  // [60]
    float* __restrict__ out)           // [32,64,64,60]
{
    extern __shared__ float smem[];
    float* Xs  = smem;            // 2940: x window; later Osm [49][60]
    float* Qs  = smem + 2940;     // 3528: q [6][49][12]
    float* KVs = smem + 6468;     // 5880: kv [6][49][20]
    // total 12348 floats = 49392 B -> 3 CTAs/SM

    const int tid = threadIdx.x;
    const int w  = blockIdx.x;
    const int b  = w / 100;
    const int wi = (w % 100) / 10;
    const int wj = w % 10;

    const float4* qwt = (const float4*)g_qkv_wt;   // [(c4*45+og)*4 + j]
    const float4* pwt = (const float4*)g_proj_wt;  // [(c4*30+jg)*2 + j]

    // ---- phase A: load x window ----
    for (int i = tid; i < 735; i += 320) {
        int t = i / 15, c4 = i % 15;
        int r  = wi * 7 + t / 7;
        int cc = wj * 7 + t % 7;
        float4 v = make_float4(0.f, 0.f, 0.f, 0.f);
        if (r < 64 && cc < 64)
            v = *(const float4*)&x[((b * 64 + r) * 64 + cc) * 60 + c4 * 4];
        *(float4*)&Xs[t * 60 + c4 * 4] = v;
    }
    __syncthreads();

    // ---- QKV GEMM: 7 tokens x 4 outputs per thread, 315 threads ----
    if (tid < 315) {
        const int og = tid / 7, tg = tid % 7;
        const int t0 = tg * 7, o0 = og * 4;
        float acc[7][4];
        #pragma unroll
        for (int j = 0; j < 4; j++) {
            float bv = __ldg(qkv_b + o0 + j);
            #pragma unroll
            for (int i = 0; i < 7; i++) acc[i][j] = bv;
        }
        #pragma unroll
        for (int c4 = 0; c4 < 15; c4++) {
            const float4* wb = qwt + (c4 * 45 + og) * 4;
            float4 wv0 = __ldg(wb);
            float4 wv1 = __ldg(wb + 1);
            float4 wv2 = __ldg(wb + 2);
            float4 wv3 = __ldg(wb + 3);
            #pragma unroll
            for (int i = 0; i < 7; i++) {
                float4 xv = *(const float4*)&Xs[(t0 + i) * 60 + c4 * 4];
                acc[i][0] = fmaf(xv.x, wv0.x, acc[i][0]);
                acc[i][0] = fmaf(xv.y, wv0.y, acc[i][0]);
                acc[i][0] = fmaf(xv.z, wv0.z, acc[i][0]);
                acc[i][0] = fmaf(xv.w, wv0.w, acc[i][0]);
                acc[i][1] = fmaf(xv.x, wv1.x, acc[i][1]);
                acc[i][1] = fmaf(xv.y, wv1.y, acc[i][1]);
                acc[i][1] = fmaf(xv.z, wv1.z, acc[i][1]);
                acc[i][1] = fmaf(xv.w, wv1.w, acc[i][1]);
                acc[i][2] = fmaf(xv.x, wv2.x, acc[i][2]);
                acc[i][2] = fmaf(xv.y, wv2.y, acc[i][2]);
                acc[i][2] = fmaf(xv.z, wv2.z, acc[i][2]);
                acc[i][2] = fmaf(xv.w, wv2.w, acc[i][2]);
                acc[i][3] = fmaf(xv.x, wv3.x, acc[i][3]);
                acc[i][3] = fmaf(xv.y, wv3.y, acc[i][3]);
                acc[i][3] = fmaf(xv.z, wv3.z, acc[i][3]);
                acc[i][3] = fmaf(xv.w, wv3.w, acc[i][3]);
            }
        }
        // scatter as aligned float2 pairs
        #pragma unroll
        for (int i = 0; i < 7; i++) {
            int t = t0 + i;
            #pragma unroll
            for (int jp = 0; jp < 2; jp++) {
                int o = o0 + 2 * jp;
                int part = o / 60, rem = o % 60;
                int hh = rem / 10, d = rem % 10;
                float* dst = (part == 0)
                    ? (Qs + hh * 588 + t * 12 + d)
                    : (KVs + hh * 980 + t * 20 + (part == 2 ? 10 : 0) + d);
                *(float2*)dst = make_float2(acc[i][2 * jp], acc[i][2 * jp + 1]);
            }
        }
    }
    __syncthreads();

    // ---- normalize: one pass, thread = (h,t) handles q row AND k row ----
    if (tid < 294) {
        const int h = tid / 49, t = tid - h * 49;
        // q row (fold exp-clamped logit scale)
        {
            float* p = Qs + h * 588 + t * 12;
            float4 a = *(float4*)p;
            float4 bq = *(float4*)(p + 4);
            float2 cq = *(float2*)(p + 8);
            float ss = a.x * a.x + a.y * a.y + a.z * a.z + a.w * a.w
                     + bq.x * bq.x + bq.y * bq.y + bq.z * bq.z + bq.w * bq.w
                     + cq.x * cq.x + cq.y * cq.y;
            float inv = rsqrtf(fmaxf(ss, 1e-24f))
                      * __expf(fminf(__ldg(ls + h), LOG100));
            a.x *= inv; a.y *= inv; a.z *= inv; a.w *= inv;
            bq.x *= inv; bq.y *= inv; bq.z *= inv; bq.w *= inv;
            cq.x *= inv; cq.y *= inv;
            *(float4*)p = a;
            *(float4*)(p + 4) = bq;
            *(float2*)(p + 8) = cq;
        }
        // k row
        {
            float* p = KVs + h * 980 + t * 20;
            float4 a = *(float4*)p;
            float4 bq = *(float4*)(p + 4);
            float2 cq = *(float2*)(p + 8);
            float ss = a.x * a.x + a.y * a.y + a.z * a.z + a.w * a.w
                     + bq.x * bq.x + bq.y * bq.y + bq.z * bq.z + bq.w * bq.w
                     + cq.x * cq.x + cq.y * cq.y;
            float inv = rsqrtf(fmaxf(ss, 1e-24f));
            a.x *= inv; a.y *= inv; a.z *= inv; a.w *= inv;
            bq.x *= inv; bq.y *= inv; bq.z *= inv; bq.w *= inv;
            cq.x *= inv; cq.y *= inv;
            *(float4*)p = a;
            *(float4*)(p + 4) = bq;
            *(float2*)(p + 8) = cq;
        }
    }
    __syncthreads();

    // ---- fused attention: 2 rows/thread, head-per-warp, STATIC-MAX ----
    float* Osm = Xs;
    const int warp = tid >> 5, lane = tid & 31;
    if (warp < 6 && lane < 25) {
        const int h = warp;
        const int r0 = 2 * lane;
        const bool two = (lane < 24);
        const float M = __expf(fminf(__ldg(ls + h), LOG100));

        const float* qp = Qs + h * 588 + r0 * 12;
        ulonglong2 Aq = *(const ulonglong2*)(qp);
        ulonglong2 Bq = *(const ulonglong2*)(qp + 4);
        ulonglong2 Cq = *(const ulonglong2*)(qp + 8);
        ulonglong2 Dq = *(const ulonglong2*)(qp + 12);
        ulonglong2 Eq = *(const ulonglong2*)(qp + 16);
        ulonglong2 Fq = *(const ulonglong2*)(qp + 20);
        const unsigned long long q00 = Aq.x, q01 = Aq.y, q02 = Bq.x,
                                 q03 = Bq.y, q04 = Cq.x;
        const unsigned long long q10 = Dq.x, q11 = Dq.y, q12 = Eq.x,
                                 q13 = Eq.y, q14 = Fq.x;

        unsigned long long o20[5], o21[5];
        #pragma unroll
        for (int i = 0; i < 5; i++) { o20[i] = 0ull; o21[i] = 0ull; }
        float l0 = 0.0f, l1 = 0.0f;

        const float* KVh = KVs + h * 980;

        #pragma unroll 7
        for (int j = 0; j < 49; j++) {
            const float* kr = KVh + j * 20;
            ulonglong2 K0 = *(const ulonglong2*)(kr);      // k0..k3
            ulonglong2 K1 = *(const ulonglong2*)(kr + 4);  // k4..k7
            ulonglong2 K2 = *(const ulonglong2*)(kr + 8);  // k8,k9 | v0,v1

            unsigned long long a0 = mul2(q00, K0.x);
            a0 = fma2(q01, K0.y, a0);
            a0 = fma2(q02, K1.x, a0);
            a0 = fma2(q03, K1.y, a0);
            a0 = fma2(q04, K2.x, a0);
            float lo, hi;
            unpack2(a0, lo, hi);
            float p0 = __expf((lo + hi) - M);

            unsigned long long a1 = mul2(q10, K0.x);
            a1 = fma2(q11, K0.y, a1);
            a1 = fma2(q12, K1.x, a1);
            a1 = fma2(q13, K1.y, a1);
            a1 = fma2(q14, K2.x, a1);
            unpack2(a1, lo, hi);
            float p1 = __expf((lo + hi) - M);

            l0 += p0; l1 += p1;
            unsigned long long pp0 = pack2(p0, p0);
            unsigned long long pp1 = pack2(p1, p1);

            ulonglong2 V1 = *(const ulonglong2*)(kr + 12);  // v2..v5
            ulonglong2 V2 = *(const ulonglong2*)(kr + 16);  // v6..v9
            o20[0] = fma2(pp0, K2.y, o20[0]);
            o20[1] = fma2(pp0, V1.x, o20[1]);
            o20[2] = fma2(pp0, V1.y, o20[2]);
            o20[3] = fma2(pp0, V2.x, o20[3]);
            o20[4] = fma2(pp0, V2.y, o20[4]);
            o21[0] = fma2(pp1, K2.y, o21[0]);
            o21[1] = fma2(pp1, V1.x, o21[1]);
            o21[2] = fma2(pp1, V1.y, o21[2]);
            o21[3] = fma2(pp1, V2.x, o21[3]);
            o21[4] = fma2(pp1, V2.y, o21[4]);
        }
        {
            float inv0 = 1.0f / l0;
            unsigned long long i20 = pack2(inv0, inv0);
            float* od = Osm + r0 * 60 + h * 10;
            #pragma unroll
            for (int i = 0; i < 5; i++)
                *(unsigned long long*)(od + 2 * i) = mul2(o20[i], i20);
        }
        if (two) {
            float inv1 = 1.0f / l1;
            unsigned long long i21 = pack2(inv1, inv1);
            float* od = Osm + (r0 + 1) * 60 + h * 10;
            #pragma unroll
            for (int i = 0; i < 5; i++)
                *(unsigned long long*)(od + 2 * i) = mul2(o21[i], i21);
        }
    }
    __syncthreads();

    // ---- output projection: 5 tokens x 2 outputs, 300 threads ----
    if (tid < 300) {
        const int jg = tid / 10, tg = tid % 10;
        const int t0 = tg * 5, o0 = jg * 2;
        float acc[5][2];
        #pragma unroll
        for (int j = 0; j < 2; j++) {
            float bv = __ldg(proj_b + o0 + j);
            #pragma unroll
            for (int i = 0; i < 5; i++) acc[i][j] = bv;
        }
        #pragma unroll
        for (int c4 = 0; c4 < 15; c4++) {
            const float4* wb = pwt + (c4 * 30 + jg) * 2;
            float4 wv0 = __ldg(wb);
            float4 wv1 = __ldg(wb + 1);
            #pragma unroll
            for (int i = 0; i < 5; i++) {
                int t = t0 + i;
                if (t < 49) {
                    float4 xv = *(const float4*)&Osm[t * 60 + c4 * 4];
                    acc[i][0] = fmaf(xv.x, wv0.x, acc[i][0]);
                    acc[i][0] = fmaf(xv.y, wv0.y, acc[i][0]);
                    acc[i][0] = fmaf(xv.z, wv0.z, acc[i][0]);
                    acc[i][0] = fmaf(xv.w, wv0.w, acc[i][0]);
                    acc[i][1] = fmaf(xv.x, wv1.x, acc[i][1]);
                    acc[i][1] = fmaf(xv.y, wv1.y, acc[i][1]);
                    acc[i][1] = fmaf(xv.z, wv1.z, acc[i][1]);
                    acc[i][1] = fmaf(xv.w, wv1.w, acc[i][1]);
                }
            }
        }
        #pragma unroll
        for (int i = 0; i < 5; i++) {
            int t = t0 + i;
            if (t < 49) {
                int r  = wi * 7 + t / 7;
                int cc = wj * 7 + t % 7;
                if (r < 64 && cc < 64) {
                    float* og = out + ((b * 64 + r) * 64 + cc) * 60 + o0;
                    *(float2*)og = make_float2(acc[i][0], acc[i][1]);
                }
            }
        }
    }
}

extern "C" void kernel_launch(void* const* d_in, const int* in_sizes, int n_in,
                              void* d_out, int out_size) {
    const float* x      = (const float*)d_in[0];
    const float* qkv_w  = (const float*)d_in[1];
    const float* qkv_b  = (const float*)d_in[2];
    const float* lscale = (const float*)d_in[3];
    const float* proj_w = (const float*)d_in[4];
    const float* proj_b = (const float*)d_in[5];
    float* out = (float*)d_out;

    transpose_weights_kernel<<<43, 256>>>(qkv_w, proj_w);

    const int smem_bytes = 12348 * 4;  // 49392 B -> 3 CTAs/SM
    cudaFuncSetAttribute(swin_win_attn_kernel,
                         cudaFuncAttributeMaxDynamicSharedMemorySize, smem_bytes);
    swin_win_attn_kernel<<<3200, 320, smem_bytes>>>(
        x, qkv_b, lscale, proj_b, out);
}

// round 15
// speedup vs baseline: 1.0925x; 1.0925x over previous
#include <cuda_runtime.h>
#include <math.h>

#define LOG100 4.605170185988092f

// B=32, H=W=64, C=60, NH=6, HD=10, WS=7, T=49; 3200 windows, 1/CTA, 320 thr.
// 3 CTAs/SM. Weights pre-transposed into __device__ scratch (line-dense LDG).
// Attention: 2 rows/thread, head-per-warp (single K/V broadcast stream/warp).
// Q: [6][49][12] (stride 12). KV: [6][49][20] = k0..k9|v0..v9.

__device__ float g_qkv_wt[10800];
__device__ float g_proj_wt[3600];

__device__ __forceinline__ unsigned long long pack2(float a, float b) {
    unsigned long long r;
    asm("mov.b64 %0, {%1, %2};" : "=l"(r) : "f"(a), "f"(b));
    return r;
}
__device__ __forceinline__ void unpack2(unsigned long long v, float& a, float& b) {
    asm("mov.b64 {%0, %1}, %2;" : "=f"(a), "=f"(b) : "l"(v));
}
__device__ __forceinline__ unsigned long long fma2(unsigned long long a,
                                                   unsigned long long b,
                                                   unsigned long long c) {
    unsigned long long r;
    asm("fma.rn.f32x2 %0, %1, %2, %3;" : "=l"(r) : "l"(a), "l"(b), "l"(c));
    return r;
}
__device__ __forceinline__ unsigned long long mul2(unsigned long long a,
                                                   unsigned long long b) {
    unsigned long long r;
    asm("mul.rn.f32x2 %0, %1, %2;" : "=l"(r) : "l"(a), "l"(b));
    return r;
}

__global__ void transpose_weights_kernel(const float* __restrict__ qkv_w,
                                         const float* __restrict__ proj_w) {
    int i = blockIdx.x * 256 + threadIdx.x;
    if (i < 10800) {
        int o = i / 60, c = i % 60;
        int c4 = c >> 2, d = c & 3, og = o >> 2, j = o & 3;
        g_qkv_wt[((c4 * 45 + og) * 4 + j) * 4 + d] = qkv_w[i];
    }
    if (i < 3600) {
        int o = i / 60, c = i % 60;
        int c4 = c >> 2, d = c & 3, jg = o >> 1, j = o & 1;
        g_proj_wt[((c4 * 30 + jg) * 2 + j) * 4 + d] = proj_w[i];
    }
}

// one attention step for both query rows of a thread
#define ATT_STEP(kr)                                                      \
    do {                                                                  \
        ulonglong2 K0 = *(const ulonglong2*)(kr);                         \
        ulonglong2 K1 = *(const ulonglong2*)((kr) + 4);                   \
        ulonglong2 K2 = *(const ulonglong2*)((kr) + 8);                   \
        unsigned long long a0 = mul2(q00, K0.x);                          \
        a0 = fma2(q01, K0.y, a0);                                         \
        a0 = fma2(q02, K1.x, a0);                                         \
        a0 = fma2(q03, K1.y, a0);                                         \
        a0 = fma2(q04, K2.x, a0);                                         \
        float lo, hi;                                                     \
        unpack2(a0, lo, hi);                                              \
        float p0 = __expf((lo + hi) - M);                                 \
        unsigned long long a1 = mul2(q10, K0.x);                          \
        a1 = fma2(q11, K0.y, a1);                                         \
        a1 = fma2(q12, K1.x, a1);                                         \
        a1 = fma2(q13, K1.y, a1);                                         \
        a1 = fma2(q14, K2.x, a1);                                         \
        unpack2(a1, lo, hi);                                              \
        float p1 = __expf((lo + hi) - M);                                 \
        l0 += p0; l1 += p1;                                               \
        unsigned long long pp0 = pack2(p0, p0);                           \
        unsigned long long pp1 = pack2(p1, p1);                           \
        ulonglong2 V1 = *(const ulonglong2*)((kr) + 12);                  \
        ulonglong2 V2 = *(const ulonglong2*)((kr) + 16);                  \
        o20[0] = fma2(pp0, K2.y, o20[0]);                                 \
        o20[1] = fma2(pp0, V1.x, o20[1]);                                 \
        o20[2] = fma2(pp0, V1.y, o20[2]);                                 \
        o20[3] = fma2(pp0, V2.x, o20[3]);                                 \
        o20[4] = fma2(pp0, V2.y, o20[4]);                                 \
        o21[0] = fma2(pp1, K2.y, o21[0]);                                 \
        o21[1] = fma2(pp1, V1.x, o21[1]);                                 \
        o21[2] = fma2(pp1, V1.y, o21[2]);                                 \
        o21[3] = fma2(pp1, V2.x, o21[3]);                                 \
        o21[4] = fma2(pp1, V2.y, o21[4]);                                 \
    } while (0)

__global__ __launch_bounds__(320, 3) void swin_win_attn_kernel(
    const float* __restrict__ x,       // [32,64,64,60]
    const float* __restrict__ qkv_b,   // [180]
    const float* __restrict__ ls,      // [6]
    const float* __restrict__ proj_b,  // [60]
    float* __restrict__ out)           // [32,64,64,60]
{
    extern __shared__ float smem[];
    float* Xs  = smem;            // 2940: x window; later Osm [49][60]
    float* Qs  = smem + 2940;     // 3528: q [6][49][12]
    float* KVs = smem + 6468;     // 5880: kv [6][49][20]
    // total 12348 floats = 49392 B -> 3 CTAs/SM

    const int tid = threadIdx.x;
    const int w  = blockIdx.x;
    const int b  = w / 100;
    const int wi = (w % 100) / 10;
    const int wj = w % 10;

    const float4* qwt = (const float4*)g_qkv_wt;   // [(c4*45+og)*4 + j]
    const float4* pwt = (const float4*)g_proj_wt;  // [(c4*30+jg)*2 + j]

    // ---- phase A: load x window ----
    for (int i = tid; i < 735; i += 320) {
        int t = i / 15, c4 = i % 15;
        int r  = wi * 7 + t / 7;
        int cc = wj * 7 + t % 7;
        float4 v = make_float4(0.f, 0.f, 0.f, 0.f);
        if (r < 64 && cc < 64)
            v = *(const float4*)&x[((b * 64 + r) * 64 + cc) * 60 + c4 * 4];
        *(float4*)&Xs[t * 60 + c4 * 4] = v;
    }
    __syncthreads();

    // ---- QKV GEMM: 7 tokens x 4 outputs per thread, 315 threads ----
    if (tid < 315) {
        const int og = tid / 7, tg = tid % 7;
        const int t0 = tg * 7, o0 = og * 4;
        float acc[7][4];
        #pragma unroll
        for (int j = 0; j < 4; j++) {
            float bv = __ldg(qkv_b + o0 + j);
            #pragma unroll
            for (int i = 0; i < 7; i++) acc[i][j] = bv;
        }
        #pragma unroll
        for (int c4 = 0; c4 < 15; c4++) {
            const float4* wb = qwt + (c4 * 45 + og) * 4;
            float4 wv0 = __ldg(wb);
            float4 wv1 = __ldg(wb + 1);
            float4 wv2 = __ldg(wb + 2);
            float4 wv3 = __ldg(wb + 3);
            #pragma unroll
            for (int i = 0; i < 7; i++) {
                float4 xv = *(const float4*)&Xs[(t0 + i) * 60 + c4 * 4];
                acc[i][0] = fmaf(xv.x, wv0.x, acc[i][0]);
                acc[i][0] = fmaf(xv.y, wv0.y, acc[i][0]);
                acc[i][0] = fmaf(xv.z, wv0.z, acc[i][0]);
                acc[i][0] = fmaf(xv.w, wv0.w, acc[i][0]);
                acc[i][1] = fmaf(xv.x, wv1.x, acc[i][1]);
                acc[i][1] = fmaf(xv.y, wv1.y, acc[i][1]);
                acc[i][1] = fmaf(xv.z, wv1.z, acc[i][1]);
                acc[i][1] = fmaf(xv.w, wv1.w, acc[i][1]);
                acc[i][2] = fmaf(xv.x, wv2.x, acc[i][2]);
                acc[i][2] = fmaf(xv.y, wv2.y, acc[i][2]);
                acc[i][2] = fmaf(xv.z, wv2.z, acc[i][2]);
                acc[i][2] = fmaf(xv.w, wv2.w, acc[i][2]);
                acc[i][3] = fmaf(xv.x, wv3.x, acc[i][3]);
                acc[i][3] = fmaf(xv.y, wv3.y, acc[i][3]);
                acc[i][3] = fmaf(xv.z, wv3.z, acc[i][3]);
                acc[i][3] = fmaf(xv.w, wv3.w, acc[i][3]);
            }
        }
        // scatter as aligned float2 pairs
        #pragma unroll
        for (int i = 0; i < 7; i++) {
            int t = t0 + i;
            #pragma unroll
            for (int jp = 0; jp < 2; jp++) {
                int o = o0 + 2 * jp;
                int part = o / 60, rem = o % 60;
                int hh = rem / 10, d = rem % 10;
                float* dst = (part == 0)
                    ? (Qs + hh * 588 + t * 12 + d)
                    : (KVs + hh * 980 + t * 20 + (part == 2 ? 10 : 0) + d);
                *(float2*)dst = make_float2(acc[i][2 * jp], acc[i][2 * jp + 1]);
            }
        }
    }
    __syncthreads();

    // ---- normalize: one pass, thread = (h,t) handles q row AND k row ----
    if (tid < 294) {
        const int h = tid / 49, t = tid - h * 49;
        {
            float* p = Qs + h * 588 + t * 12;
            float4 a = *(float4*)p;
            float4 bq = *(float4*)(p + 4);
            float2 cq = *(float2*)(p + 8);
            float ss = a.x * a.x + a.y * a.y + a.z * a.z + a.w * a.w
                     + bq.x * bq.x + bq.y * bq.y + bq.z * bq.z + bq.w * bq.w
                     + cq.x * cq.x + cq.y * cq.y;
            float inv = rsqrtf(fmaxf(ss, 1e-24f))
                      * __expf(fminf(__ldg(ls + h), LOG100));
            a.x *= inv; a.y *= inv; a.z *= inv; a.w *= inv;
            bq.x *= inv; bq.y *= inv; bq.z *= inv; bq.w *= inv;
            cq.x *= inv; cq.y *= inv;
            *(float4*)p = a;
            *(float4*)(p + 4) = bq;
            *(float2*)(p + 8) = cq;
        }
        {
            float* p = KVs + h * 980 + t * 20;
            float4 a = *(float4*)p;
            float4 bq = *(float4*)(p + 4);
            float2 cq = *(float2*)(p + 8);
            float ss = a.x * a.x + a.y * a.y + a.z * a.z + a.w * a.w
                     + bq.x * bq.x + bq.y * bq.y + bq.z * bq.z + bq.w * bq.w
                     + cq.x * cq.x + cq.y * cq.y;
            float inv = rsqrtf(fmaxf(ss, 1e-24f));
            a.x *= inv; a.y *= inv; a.z *= inv; a.w *= inv;
            bq.x *= inv; bq.y *= inv; bq.z *= inv; bq.w *= inv;
            cq.x *= inv; cq.y *= inv;
            *(float4*)p = a;
            *(float4*)(p + 4) = bq;
            *(float2*)(p + 8) = cq;
        }
    }
    __syncthreads();

    // ---- fused attention: 2 rows/thread, head-per-warp, STATIC-MAX ----
    float* Osm = Xs;
    const int warp = tid >> 5, lane = tid & 31;
    if (warp < 6 && lane < 25) {
        const int h = warp;
        const int r0 = 2 * lane;
        const bool two = (lane < 24);
        const float M = __expf(fminf(__ldg(ls + h), LOG100));

        const float* qp = Qs + h * 588 + r0 * 12;
        ulonglong2 Aq = *(const ulonglong2*)(qp);
        ulonglong2 Bq = *(const ulonglong2*)(qp + 4);
        ulonglong2 Cq = *(const ulonglong2*)(qp + 8);
        ulonglong2 Dq = *(const ulonglong2*)(qp + 12);
        ulonglong2 Eq = *(const ulonglong2*)(qp + 16);
        ulonglong2 Fq = *(const ulonglong2*)(qp + 20);
        const unsigned long long q00 = Aq.x, q01 = Aq.y, q02 = Bq.x,
                                 q03 = Bq.y, q04 = Cq.x;
        const unsigned long long q10 = Dq.x, q11 = Dq.y, q12 = Eq.x,
                                 q13 = Eq.y, q14 = Fq.x;

        unsigned long long o20[5], o21[5];
        #pragma unroll
        for (int i = 0; i < 5; i++) { o20[i] = 0ull; o21[i] = 0ull; }
        float l0 = 0.0f, l1 = 0.0f;

        const float* kr = KVs + h * 980;

        // unroll-2 with pointer increment: low ALU, low register pressure
        #pragma unroll 1
        for (int j = 0; j < 24; j++) {
            ATT_STEP(kr);
            ATT_STEP(kr + 20);
            kr += 40;
        }
        ATT_STEP(kr);  // row 48

        {
            float inv0 = 1.0f / l0;
            unsigned long long i20 = pack2(inv0, inv0);
            float* od = Osm + r0 * 60 + h * 10;
            #pragma unroll
            for (int i = 0; i < 5; i++)
                *(unsigned long long*)(od + 2 * i) = mul2(o20[i], i20);
        }
        if (two) {
            float inv1 = 1.0f / l1;
            unsigned long long i21 = pack2(inv1, inv1);
            float* od = Osm + (r0 + 1) * 60 + h * 10;
            #pragma unroll
            for (int i = 0; i < 5; i++)
                *(unsigned long long*)(od + 2 * i) = mul2(o21[i], i21);
        }
    }
    __syncthreads();

    // ---- output projection: 7 tokens x 2 outputs, 210 threads ----
    if (tid < 210) {
        const int jg = tid / 7, tg = tid % 7;
        const int t0 = tg * 7, o0 = jg * 2;
        float acc[7][2];
        #pragma unroll
        for (int j = 0; j < 2; j++) {
            float bv = __ldg(proj_b + o0 + j);
            #pragma unroll
            for (int i = 0; i < 7; i++) acc[i][j] = bv;
        }
        #pragma unroll
        for (int c4 = 0; c4 < 15; c4++) {
            const float4* wb = pwt + (c4 * 30 + jg) * 2;
            float4 wv0 = __ldg(wb);
            float4 wv1 = __ldg(wb + 1);
            #pragma unroll
            for (int i = 0; i < 7; i++) {
                float4 xv = *(const float4*)&Osm[(t0 + i) * 60 + c4 * 4];
                acc[i][0] = fmaf(xv.x, wv0.x, acc[i][0]);
                acc[i][0] = fmaf(xv.y, wv0.y, acc[i][0]);
                acc[i][0] = fmaf(xv.z, wv0.z, acc[i][0]);
                acc[i][0] = fmaf(xv.w, wv0.w, acc[i][0]);
                acc[i][1] = fmaf(xv.x, wv1.x, acc[i][1]);
                acc[i][1] = fmaf(xv.y, wv1.y, acc[i][1]);
                acc[i][1] = fmaf(xv.z, wv1.z, acc[i][1]);
                acc[i][1] = fmaf(xv.w, wv1.w, acc[i][1]);
            }
        }
        #pragma unroll
        for (int i = 0; i < 7; i++) {
            int t = t0 + i;
            int r  = wi * 7 + t / 7;
            int cc = wj * 7 + t % 7;
            if (r < 64 && cc < 64) {
                float* og = out + ((b * 64 + r) * 64 + cc) * 60 + o0;
                *(float2*)og = make_float2(acc[i][0], acc[i][1]);
            }
        }
    }
}

extern "C" void kernel_launch(void* const* d_in, const int* in_sizes, int n_in,
                              void* d_out, int out_size) {
    const float* x      = (const float*)d_in[0];
    const float* qkv_w  = (const float*)d_in[1];
    const float* qkv_b  = (const float*)d_in[2];
    const float* lscale = (const float*)d_in[3];
    const float* proj_w = (const float*)d_in[4];
    const float* proj_b = (const float*)d_in[5];
    float* out = (float*)d_out;

    transpose_weights_kernel<<<43, 256>>>(qkv_w, proj_w);

    const int smem_bytes = 12348 * 4;  // 49392 B -> 3 CTAs/SM
    cudaFuncSetAttribute(swin_win_attn_kernel,
                         cudaFuncAttributeMaxDynamicSharedMemorySize, smem_bytes);
    swin_win_attn_kernel<<<3200, 320, smem_bytes>>>(
        x, qkv_b, lscale, proj_b, out);
}

// round 16
// speedup vs baseline: 1.0935x; 1.0009x over previous
#include <cuda_runtime.h>
#include <math.h>

#define LOG100 4.605170185988092f
#define LOG2E  1.4426950408889634f

// B=32, H=W=64, C=60, NH=6, HD=10, WS=7, T=49; 3200 windows, 1/CTA, 320 thr.
// 3 CTAs/SM. Weights pre-transposed into __device__ scratch (line-dense LDG).
// Attention: 2 rows/thread, head-per-warp, static-max softmax with log2e and
// -M' folded into the dot product (raw ex2, no FMUL/FADD per exp).
// Q: [6][49][12] (stride 12, holds log2e*scale*qn). KV: [6][49][20] = k|v.

__device__ float g_qkv_wt[10800];
__device__ float g_proj_wt[3600];

__device__ __forceinline__ unsigned long long pack2(float a, float b) {
    unsigned long long r;
    asm("mov.b64 %0, {%1, %2};" : "=l"(r) : "f"(a), "f"(b));
    return r;
}
__device__ __forceinline__ void unpack2(unsigned long long v, float& a, float& b) {
    asm("mov.b64 {%0, %1}, %2;" : "=f"(a), "=f"(b) : "l"(v));
}
__device__ __forceinline__ unsigned long long fma2(unsigned long long a,
                                                   unsigned long long b,
                                                   unsigned long long c) {
    unsigned long long r;
    asm("fma.rn.f32x2 %0, %1, %2, %3;" : "=l"(r) : "l"(a), "l"(b), "l"(c));
    return r;
}
__device__ __forceinline__ unsigned long long mul2(unsigned long long a,
                                                   unsigned long long b) {
    unsigned long long r;
    asm("mul.rn.f32x2 %0, %1, %2;" : "=l"(r) : "l"(a), "l"(b));
    return r;
}
__device__ __forceinline__ float ex2f(float x) {
    float r;
    asm("ex2.approx.ftz.f32 %0, %1;" : "=f"(r) : "f"(x));
    return r;
}

__global__ void transpose_weights_kernel(const float* __restrict__ qkv_w,
                                         const float* __restrict__ proj_w) {
    int i = blockIdx.x * 256 + threadIdx.x;
    if (i < 10800) {
        int o = i / 60, c = i % 60;
        int c4 = c >> 2, d = c & 3, og = o >> 2, j = o & 3;
        g_qkv_wt[((c4 * 45 + og) * 4 + j) * 4 + d] = qkv_w[i];
    }
    if (i < 3600) {
        int o = i / 60, c = i % 60;
        int c4 = c >> 2, d = c & 3, jg = o >> 1, j = o & 1;
        g_proj_wt[((c4 * 30 + jg) * 2 + j) * 4 + d] = proj_w[i];
    }
}

// one attention step for both query rows; dot accumulates (log2e*s - M')
// directly via the mneg init, so p = ex2(lo+hi) with no extra scalar ops.
#define ATT_STEP(kr)                                                      \
    do {                                                                  \
        ulonglong2 K0 = *(const ulonglong2*)(kr);                         \
        ulonglong2 K1 = *(const ulonglong2*)((kr) + 4);                   \
        ulonglong2 K2 = *(const ulonglong2*)((kr) + 8);                   \
        unsigned long long a0 = fma2(q00, K0.x, mneg);                    \
        a0 = fma2(q01, K0.y, a0);                                         \
        a0 = fma2(q02, K1.x, a0);                                         \
        a0 = fma2(q03, K1.y, a0);                                         \
        a0 = fma2(q04, K2.x, a0);                                         \
        float lo, hi;                                                     \
        unpack2(a0, lo, hi);                                              \
        float p0 = ex2f(lo + hi);                                         \
        unsigned long long a1 = fma2(q10, K0.x, mneg);                    \
        a1 = fma2(q11, K0.y, a1);                                         \
        a1 = fma2(q12, K1.x, a1);                                         \
        a1 = fma2(q13, K1.y, a1);                                         \
        a1 = fma2(q14, K2.x, a1);                                         \
        unpack2(a1, lo, hi);                                              \
        float p1 = ex2f(lo + hi);                                         \
        l0 += p0; l1 += p1;                                               \
        unsigned long long pp0 = pack2(p0, p0);                           \
        unsigned long long pp1 = pack2(p1, p1);                           \
        ulonglong2 V1 = *(const ulonglong2*)((kr) + 12);                  \
        ulonglong2 V2 = *(const ulonglong2*)((kr) + 16);                  \
        o20[0] = fma2(pp0, K2.y, o20[0]);                                 \
        o20[1] = fma2(pp0, V1.x, o20[1]);                                 \
        o20[2] = fma2(pp0, V1.y, o20[2]);                                 \
        o20[3] = fma2(pp0, V2.x, o20[3]);                                 \
        o20[4] = fma2(pp0, V2.y, o20[4]);                                 \
        o21[0] = fma2(pp1, K2.y, o21[0]);                                 \
        o21[1] = fma2(pp1, V1.x, o21[1]);                                 \
        o21[2] = fma2(pp1, V1.y, o21[2]);                                 \
        o21[3] = fma2(pp1, V2.x, o21[3]);                                 \
        o21[4] = fma2(pp1, V2.y, o21[4]);                                 \
    } while (0)

__global__ __launch_bounds__(320, 3) void swin_win_attn_kernel(
    const float* __restrict__ x,       // [32,64,64,60]
    const float* __restrict__ qkv_b,   // [180]
    const float* __restrict__ ls,      // [6]
    const float* __restrict__ proj_b,  // [60]
    float* __restrict__ out)           // [32,64,64,60]
{
    extern __shared__ float smem[];
    float* Xs  = smem;            // 2940: x window; later Osm [49][60]
    float* Qs  = smem + 2940;     // 3528: q [6][49][12]
    float* KVs = smem + 6468;     // 5880: kv [6][49][20]
    // total 12348 floats = 49392 B -> 3 CTAs/SM

    const int tid = threadIdx.x;
    const int w  = blockIdx.x;
    const int b  = w / 100;
    const int wi = (w % 100) / 10;
    const int wj = w % 10;

    const float4* qwt = (const float4*)g_qkv_wt;   // [(c4*45+og)*4 + j]
    const float4* pwt = (const float4*)g_proj_wt;  // [(c4*30+jg)*2 + j]

    // ---- phase A: load x window ----
    for (int i = tid; i < 735; i += 320) {
        int t = i / 15, c4 = i % 15;
        int r  = wi * 7 + t / 7;
        int cc = wj * 7 + t % 7;
        float4 v = make_float4(0.f, 0.f, 0.f, 0.f);
        if (r < 64 && cc < 64)
            v = *(const float4*)&x[((b * 64 + r) * 64 + cc) * 60 + c4 * 4];
        *(float4*)&Xs[t * 60 + c4 * 4] = v;
    }
    __syncthreads();

    // ---- QKV GEMM: 7 tokens x 4 outputs per thread, 315 threads ----
    if (tid < 315) {
        const int og = tid / 7, tg = tid % 7;
        const int t0 = tg * 7, o0 = og * 4;
        float acc[7][4];
        #pragma unroll
        for (int j = 0; j < 4; j++) {
            float bv = __ldg(qkv_b + o0 + j);
            #pragma unroll
            for (int i = 0; i < 7; i++) acc[i][j] = bv;
        }
        #pragma unroll
        for (int c4 = 0; c4 < 15; c4++) {
            const float4* wb = qwt + (c4 * 45 + og) * 4;
            float4 wv0 = __ldg(wb);
            float4 wv1 = __ldg(wb + 1);
            float4 wv2 = __ldg(wb + 2);
            float4 wv3 = __ldg(wb + 3);
            #pragma unroll
            for (int i = 0; i < 7; i++) {
                float4 xv = *(const float4*)&Xs[(t0 + i) * 60 + c4 * 4];
                acc[i][0] = fmaf(xv.x, wv0.x, acc[i][0]);
                acc[i][0] = fmaf(xv.y, wv0.y, acc[i][0]);
                acc[i][0] = fmaf(xv.z, wv0.z, acc[i][0]);
                acc[i][0] = fmaf(xv.w, wv0.w, acc[i][0]);
                acc[i][1] = fmaf(xv.x, wv1.x, acc[i][1]);
                acc[i][1] = fmaf(xv.y, wv1.y, acc[i][1]);
                acc[i][1] = fmaf(xv.z, wv1.z, acc[i][1]);
                acc[i][1] = fmaf(xv.w, wv1.w, acc[i][1]);
                acc[i][2] = fmaf(xv.x, wv2.x, acc[i][2]);
                acc[i][2] = fmaf(xv.y, wv2.y, acc[i][2]);
                acc[i][2] = fmaf(xv.z, wv2.z, acc[i][2]);
                acc[i][2] = fmaf(xv.w, wv2.w, acc[i][2]);
                acc[i][3] = fmaf(xv.x, wv3.x, acc[i][3]);
                acc[i][3] = fmaf(xv.y, wv3.y, acc[i][3]);
                acc[i][3] = fmaf(xv.z, wv3.z, acc[i][3]);
                acc[i][3] = fmaf(xv.w, wv3.w, acc[i][3]);
            }
        }
        // scatter as aligned float2 pairs
        #pragma unroll
        for (int i = 0; i < 7; i++) {
            int t = t0 + i;
            #pragma unroll
            for (int jp = 0; jp < 2; jp++) {
                int o = o0 + 2 * jp;
                int part = o / 60, rem = o % 60;
                int hh = rem / 10, d = rem % 10;
                float* dst = (part == 0)
                    ? (Qs + hh * 588 + t * 12 + d)
                    : (KVs + hh * 980 + t * 20 + (part == 2 ? 10 : 0) + d);
                *(float2*)dst = make_float2(acc[i][2 * jp], acc[i][2 * jp + 1]);
            }
        }
    }
    __syncthreads();

    // ---- normalize: one pass, thread = (h,t) handles q row AND k row ----
    // q gets scale * log2e folded in (for the raw-ex2 softmax)
    if (tid < 294) {
        const int h = tid / 49, t = tid - h * 49;
        {
            float* p = Qs + h * 588 + t * 12;
            float4 a = *(float4*)p;
            float4 bq = *(float4*)(p + 4);
            float2 cq = *(float2*)(p + 8);
            float ss = a.x * a.x + a.y * a.y + a.z * a.z + a.w * a.w
                     + bq.x * bq.x + bq.y * bq.y + bq.z * bq.z + bq.w * bq.w
                     + cq.x * cq.x + cq.y * cq.y;
            float inv = rsqrtf(fmaxf(ss, 1e-24f))
                      * __expf(fminf(__ldg(ls + h), LOG100)) * LOG2E;
            a.x *= inv; a.y *= inv; a.z *= inv; a.w *= inv;
            bq.x *= inv; bq.y *= inv; bq.z *= inv; bq.w *= inv;
            cq.x *= inv; cq.y *= inv;
            *(float4*)p = a;
            *(float4*)(p + 4) = bq;
            *(float2*)(p + 8) = cq;
        }
        {
            float* p = KVs + h * 980 + t * 20;
            float4 a = *(float4*)p;
            float4 bq = *(float4*)(p + 4);
            float2 cq = *(float2*)(p + 8);
            float ss = a.x * a.x + a.y * a.y + a.z * a.z + a.w * a.w
                     + bq.x * bq.x + bq.y * bq.y + bq.z * bq.z + bq.w * bq.w
                     + cq.x * cq.x + cq.y * cq.y;
            float inv = rsqrtf(fmaxf(ss, 1e-24f));
            a.x *= inv; a.y *= inv; a.z *= inv; a.w *= inv;
            bq.x *= inv; bq.y *= inv; bq.z *= inv; bq.w *= inv;
            cq.x *= inv; cq.y *= inv;
            *(float4*)p = a;
            *(float4*)(p + 4) = bq;
            *(float2*)(p + 8) = cq;
        }
    }
    __syncthreads();

    // ---- fused attention: 2 rows/thread, head-per-warp, folded-ex2 softmax ----
    float* Osm = Xs;
    const int warp = tid >> 5, lane = tid & 31;
    if (warp < 6 && lane < 25) {
        const int h = warp;
        const int r0 = 2 * lane;
        const bool two = (lane < 24);
        const float Mp = __expf(fminf(__ldg(ls + h), LOG100)) * LOG2E;
        const unsigned long long mneg = pack2(-Mp, 0.0f);

        const float* qp = Qs + h * 588 + r0 * 12;
        ulonglong2 Aq = *(const ulonglong2*)(qp);
        ulonglong2 Bq = *(const ulonglong2*)(qp + 4);
        ulonglong2 Cq = *(const ulonglong2*)(qp + 8);
        ulonglong2 Dq = *(const ulonglong2*)(qp + 12);
        ulonglong2 Eq = *(const ulonglong2*)(qp + 16);
        ulonglong2 Fq = *(const ulonglong2*)(qp + 20);
        const unsigned long long q00 = Aq.x, q01 = Aq.y, q02 = Bq.x,
                                 q03 = Bq.y, q04 = Cq.x;
        const unsigned long long q10 = Dq.x, q11 = Dq.y, q12 = Eq.x,
                                 q13 = Eq.y, q14 = Fq.x;

        unsigned long long o20[5], o21[5];
        #pragma unroll
        for (int i = 0; i < 5; i++) { o20[i] = 0ull; o21[i] = 0ull; }
        float l0 = 0.0f, l1 = 0.0f;

        const float* kr = KVs + h * 980;

        #pragma unroll 1
        for (int j = 0; j < 24; j++) {
            ATT_STEP(kr);
            ATT_STEP(kr + 20);
            kr += 40;
        }
        ATT_STEP(kr);  // row 48

        {
            float inv0 = 1.0f / l0;
            unsigned long long i20 = pack2(inv0, inv0);
            float* od = Osm + r0 * 60 + h * 10;
            #pragma unroll
            for (int i = 0; i < 5; i++)
                *(unsigned long long*)(od + 2 * i) = mul2(o20[i], i20);
        }
        if (two) {
            float inv1 = 1.0f / l1;
            unsigned long long i21 = pack2(inv1, inv1);
            float* od = Osm + (r0 + 1) * 60 + h * 10;
            #pragma unroll
            for (int i = 0; i < 5; i++)
                *(unsigned long long*)(od + 2 * i) = mul2(o21[i], i21);
        }
    }
    __syncthreads();

    // ---- output projection: 7 tokens x 2 outputs, 210 threads ----
    if (tid < 210) {
        const int jg = tid / 7, tg = tid % 7;
        const int t0 = tg * 7, o0 = jg * 2;
        float acc[7][2];
        #pragma unroll
        for (int j = 0; j < 2; j++) {
            float bv = __ldg(proj_b + o0 + j);
            #pragma unroll
            for (int i = 0; i < 7; i++) acc[i][j] = bv;
        }
        #pragma unroll
        for (int c4 = 0; c4 < 15; c4++) {
            const float4* wb = pwt + (c4 * 30 + jg) * 2;
            float4 wv0 = __ldg(wb);
            float4 wv1 = __ldg(wb + 1);
            #pragma unroll
            for (int i = 0; i < 7; i++) {
                float4 xv = *(const float4*)&Osm[(t0 + i) * 60 + c4 * 4];
                acc[i][0] = fmaf(xv.x, wv0.x, acc[i][0]);
                acc[i][0] = fmaf(xv.y, wv0.y, acc[i][0]);
                acc[i][0] = fmaf(xv.z, wv0.z, acc[i][0]);
                acc[i][0] = fmaf(xv.w, wv0.w, acc[i][0]);
                acc[i][1] = fmaf(xv.x, wv1.x, acc[i][1]);
                acc[i][1] = fmaf(xv.y, wv1.y, acc[i][1]);
                acc[i][1] = fmaf(xv.z, wv1.z, acc[i][1]);
                acc[i][1] = fmaf(xv.w, wv1.w, acc[i][1]);
            }
        }
        #pragma unroll
        for (int i = 0; i < 7; i++) {
            int t = t0 + i;
            int r  = wi * 7 + t / 7;
            int cc = wj * 7 + t % 7;
            if (r < 64 && cc < 64) {
                float* og = out + ((b * 64 + r) * 64 + cc) * 60 + o0;
                *(float2*)og = make_float2(acc[i][0], acc[i][1]);
            }
        }
    }
}

extern "C" void kernel_launch(void* const* d_in, const int* in_sizes, int n_in,
                              void* d_out, int out_size) {
    const float* x      = (const float*)d_in[0];
    const float* qkv_w  = (const float*)d_in[1];
    const float* qkv_b  = (const float*)d_in[2];
    const float* lscale = (const float*)d_in[3];
    const float* proj_w = (const float*)d_in[4];
    const float* proj_b = (const float*)d_in[5];
    float* out = (float*)d_out;

    transpose_weights_kernel<<<43, 256>>>(qkv_w, proj_w);

    const int smem_bytes = 12348 * 4;  // 49392 B -> 3 CTAs/SM
    cudaFuncSetAttribute(swin_win_attn_kernel,
                         cudaFuncAttributeMaxDynamicSharedMemorySize, smem_bytes);
    swin_win_attn_kernel<<<3200, 320, smem_bytes>>>(
        x, qkv_b, lscale, proj_b, out);
}

// round 17
// speedup vs baseline: 1.1482x; 1.0500x over previous
#include <cuda_runtime.h>
#include <math.h>

#define LOG100 4.605170185988092f
#define LOG2E  1.4426950408889634f

// B=32, H=W=64, C=60, NH=6, HD=10, WS=7, T=49; 3200 windows, 1/CTA, 320 thr.
// 3 CTAs/SM. Broadcast-x GEMM mapping: warp shares token group -> x LDS are
// broadcasts; weights laid out j-major so each LDG.128 is 32 consecutive
// float4s (4 lines). Attention: 2 rows/thread, head-per-warp, folded-ex2.
// Q: [6][49][12]. KV: [6][49][20] = k0..k9|v0..v9.

__device__ float g_qkv_wt[10800];   // [((j*15+c4)*45+og)*4+d]
__device__ float g_proj_wt[3600];   // [((j*15+c4)*30+jg)*4+d]

__device__ __forceinline__ unsigned long long pack2(float a, float b) {
    unsigned long long r;
    asm("mov.b64 %0, {%1, %2};" : "=l"(r) : "f"(a), "f"(b));
    return r;
}
__device__ __forceinline__ void unpack2(unsigned long long v, float& a, float& b) {
    asm("mov.b64 {%0, %1}, %2;" : "=f"(a), "=f"(b) : "l"(v));
}
__device__ __forceinline__ unsigned long long fma2(unsigned long long a,
                                                   unsigned long long b,
                                                   unsigned long long c) {
    unsigned long long r;
    asm("fma.rn.f32x2 %0, %1, %2, %3;" : "=l"(r) : "l"(a), "l"(b), "l"(c));
    return r;
}
__device__ __forceinline__ unsigned long long mul2(unsigned long long a,
                                                   unsigned long long b) {
    unsigned long long r;
    asm("mul.rn.f32x2 %0, %1, %2;" : "=l"(r) : "l"(a), "l"(b));
    return r;
}
__device__ __forceinline__ float ex2f(float x) {
    float r;
    asm("ex2.approx.ftz.f32 %0, %1;" : "=f"(r) : "f"(x));
    return r;
}

__global__ void transpose_weights_kernel(const float* __restrict__ qkv_w,
                                         const float* __restrict__ proj_w) {
    int i = blockIdx.x * 256 + threadIdx.x;
    if (i < 10800) {
        int o = i / 60, c = i % 60;
        int c4 = c >> 2, d = c & 3, og = o >> 2, j = o & 3;
        g_qkv_wt[((j * 15 + c4) * 45 + og) * 4 + d] = qkv_w[i];
    }
    if (i < 3600) {
        int o = i / 60, c = i % 60;
        int c4 = c >> 2, d = c & 3, jg = o >> 1, j = o & 1;
        g_proj_wt[((j * 15 + c4) * 30 + jg) * 4 + d] = proj_w[i];
    }
}

// one attention step for both query rows; dot accumulates (log2e*s - M')
#define ATT_STEP(kr)                                                      \
    do {                                                                  \
        ulonglong2 K0 = *(const ulonglong2*)(kr);                         \
        ulonglong2 K1 = *(const ulonglong2*)((kr) + 4);                   \
        ulonglong2 K2 = *(const ulonglong2*)((kr) + 8);                   \
        unsigned long long a0 = fma2(q00, K0.x, mneg);                    \
        a0 = fma2(q01, K0.y, a0);                                         \
        a0 = fma2(q02, K1.x, a0);                                         \
        a0 = fma2(q03, K1.y, a0);                                         \
        a0 = fma2(q04, K2.x, a0);                                         \
        float lo, hi;                                                     \
        unpack2(a0, lo, hi);                                              \
        float p0 = ex2f(lo + hi);                                         \
        unsigned long long a1 = fma2(q10, K0.x, mneg);                    \
        a1 = fma2(q11, K0.y, a1);                                         \
        a1 = fma2(q12, K1.x, a1);                                         \
        a1 = fma2(q13, K1.y, a1);                                         \
        a1 = fma2(q14, K2.x, a1);                                         \
        unpack2(a1, lo, hi);                                              \
        float p1 = ex2f(lo + hi);                                         \
        l0 += p0; l1 += p1;                                               \
        unsigned long long pp0 = pack2(p0, p0);                           \
        unsigned long long pp1 = pack2(p1, p1);                           \
        ulonglong2 V1 = *(const ulonglong2*)((kr) + 12);                  \
        ulonglong2 V2 = *(const ulonglong2*)((kr) + 16);                  \
        o20[0] = fma2(pp0, K2.y, o20[0]);                                 \
        o20[1] = fma2(pp0, V1.x, o20[1]);                                 \
        o20[2] = fma2(pp0, V1.y, o20[2]);                                 \
        o20[3] = fma2(pp0, V2.x, o20[3]);                                 \
        o20[4] = fma2(pp0, V2.y, o20[4]);                                 \
        o21[0] = fma2(pp1, K2.y, o21[0]);                                 \
        o21[1] = fma2(pp1, V1.x, o21[1]);                                 \
        o21[2] = fma2(pp1, V1.y, o21[2]);                                 \
        o21[3] = fma2(pp1, V2.x, o21[3]);                                 \
        o21[4] = fma2(pp1, V2.y, o21[4]);                                 \
    } while (0)

__global__ __launch_bounds__(320, 3) void swin_win_attn_kernel(
    const float* __restrict__ x,       // [32,64,64,60]
    const float* __restrict__ qkv_b,   // [180]
    const float* __restrict__ ls,      // [6]
    const float* __restrict__ proj_b,  // [60]
    float* __restrict__ out)           // [32,64,64,60]
{
    extern __shared__ float smem[];
    float* Xs  = smem;            // 2940: x window; later Osm [49][60]
    float* Qs  = smem + 2940;     // 3528: q [6][49][12]
    float* KVs = smem + 6468;     // 5880: kv [6][49][20]
    // total 12348 floats = 49392 B -> 3 CTAs/SM

    const int tid = threadIdx.x;
    const int w  = blockIdx.x;
    const int b  = w / 100;
    const int wi = (w % 100) / 10;
    const int wj = w % 10;

    const float4* qwt = (const float4*)g_qkv_wt;   // [(j*15+c4)*45 + og]
    const float4* pwt = (const float4*)g_proj_wt;  // [(j*15+c4)*30 + jg]

    // ---- phase A: load x window ----
    for (int i = tid; i < 735; i += 320) {
        int t = i / 15, c4 = i % 15;
        int r  = wi * 7 + t / 7;
        int cc = wj * 7 + t % 7;
        float4 v = make_float4(0.f, 0.f, 0.f, 0.f);
        if (r < 64 && cc < 64)
            v = *(const float4*)&x[((b * 64 + r) * 64 + cc) * 60 + c4 * 4];
        *(float4*)&Xs[t * 60 + c4 * 4] = v;
    }
    __syncthreads();

    // ---- QKV GEMM: 7 tokens x 4 outputs, 315 threads ----
    // tg = tid/45 (warp-shared -> broadcast x LDS), og = tid%45 (coalesced LDG)
    if (tid < 315) {
        const int tg = tid / 45, og = tid % 45;
        const int t0 = tg * 7, o0 = og * 4;
        float acc[7][4];
        #pragma unroll
        for (int j = 0; j < 4; j++) {
            float bv = __ldg(qkv_b + o0 + j);
            #pragma unroll
            for (int i = 0; i < 7; i++) acc[i][j] = bv;
        }
        #pragma unroll
        for (int c4 = 0; c4 < 15; c4++) {
            float4 wv0 = __ldg(qwt + (c4)       * 45 + og);       // j=0
            float4 wv1 = __ldg(qwt + (15 + c4)  * 45 + og);       // j=1
            float4 wv2 = __ldg(qwt + (30 + c4)  * 45 + og);       // j=2
            float4 wv3 = __ldg(qwt + (45 + c4)  * 45 + og);       // j=3
            #pragma unroll
            for (int i = 0; i < 7; i++) {
                float4 xv = *(const float4*)&Xs[(t0 + i) * 60 + c4 * 4];
                acc[i][0] = fmaf(xv.x, wv0.x, acc[i][0]);
                acc[i][0] = fmaf(xv.y, wv0.y, acc[i][0]);
                acc[i][0] = fmaf(xv.z, wv0.z, acc[i][0]);
                acc[i][0] = fmaf(xv.w, wv0.w, acc[i][0]);
                acc[i][1] = fmaf(xv.x, wv1.x, acc[i][1]);
                acc[i][1] = fmaf(xv.y, wv1.y, acc[i][1]);
                acc[i][1] = fmaf(xv.z, wv1.z, acc[i][1]);
                acc[i][1] = fmaf(xv.w, wv1.w, acc[i][1]);
                acc[i][2] = fmaf(xv.x, wv2.x, acc[i][2]);
                acc[i][2] = fmaf(xv.y, wv2.y, acc[i][2]);
                acc[i][2] = fmaf(xv.z, wv2.z, acc[i][2]);
                acc[i][2] = fmaf(xv.w, wv2.w, acc[i][2]);
                acc[i][3] = fmaf(xv.x, wv3.x, acc[i][3]);
                acc[i][3] = fmaf(xv.y, wv3.y, acc[i][3]);
                acc[i][3] = fmaf(xv.z, wv3.z, acc[i][3]);
                acc[i][3] = fmaf(xv.w, wv3.w, acc[i][3]);
            }
        }
        // scatter as aligned float2 pairs
        #pragma unroll
        for (int i = 0; i < 7; i++) {
            int t = t0 + i;
            #pragma unroll
            for (int jp = 0; jp < 2; jp++) {
                int o = o0 + 2 * jp;
                int part = o / 60, rem = o % 60;
                int hh = rem / 10, d = rem % 10;
                float* dst = (part == 0)
                    ? (Qs + hh * 588 + t * 12 + d)
                    : (KVs + hh * 980 + t * 20 + (part == 2 ? 10 : 0) + d);
                *(float2*)dst = make_float2(acc[i][2 * jp], acc[i][2 * jp + 1]);
            }
        }
    }
    __syncthreads();

    // ---- normalize: one pass, thread = (h,t) handles q row AND k row ----
    // q gets scale * log2e folded in (for the raw-ex2 softmax)
    if (tid < 294) {
        const int h = tid / 49, t = tid - h * 49;
        {
            float* p = Qs + h * 588 + t * 12;
            float4 a = *(float4*)p;
            float4 bq = *(float4*)(p + 4);
            float2 cq = *(float2*)(p + 8);
            float ss = a.x * a.x + a.y * a.y + a.z * a.z + a.w * a.w
                     + bq.x * bq.x + bq.y * bq.y + bq.z * bq.z + bq.w * bq.w
                     + cq.x * cq.x + cq.y * cq.y;
            float inv = rsqrtf(fmaxf(ss, 1e-24f))
                      * __expf(fminf(__ldg(ls + h), LOG100)) * LOG2E;
            a.x *= inv; a.y *= inv; a.z *= inv; a.w *= inv;
            bq.x *= inv; bq.y *= inv; bq.z *= inv; bq.w *= inv;
            cq.x *= inv; cq.y *= inv;
            *(float4*)p = a;
            *(float4*)(p + 4) = bq;
            *(float2*)(p + 8) = cq;
        }
        {
            float* p = KVs + h * 980 + t * 20;
            float4 a = *(float4*)p;
            float4 bq = *(float4*)(p + 4);
            float2 cq = *(float2*)(p + 8);
            float ss = a.x * a.x + a.y * a.y + a.z * a.z + a.w * a.w
                     + bq.x * bq.x + bq.y * bq.y + bq.z * bq.z + bq.w * bq.w
                     + cq.x * cq.x + cq.y * cq.y;
            float inv = rsqrtf(fmaxf(ss, 1e-24f));
            a.x *= inv; a.y *= inv; a.z *= inv; a.w *= inv;
            bq.x *= inv; bq.y *= inv; bq.z *= inv; bq.w *= inv;
            cq.x *= inv; cq.y *= inv;
            *(float4*)p = a;
            *(float4*)(p + 4) = bq;
            *(float2*)(p + 8) = cq;
        }
    }
    __syncthreads();

    // ---- fused attention: 2 rows/thread, head-per-warp, folded-ex2 softmax ----
    float* Osm = Xs;
    const int warp = tid >> 5, lane = tid & 31;
    if (warp < 6 && lane < 25) {
        const int h = warp;
        const int r0 = 2 * lane;
        const bool two = (lane < 24);
        const float Mp = __expf(fminf(__ldg(ls + h), LOG100)) * LOG2E;
        const unsigned long long mneg = pack2(-Mp, 0.0f);

        const float* qp = Qs + h * 588 + r0 * 12;
        ulonglong2 Aq = *(const ulonglong2*)(qp);
        ulonglong2 Bq = *(const ulonglong2*)(qp + 4);
        ulonglong2 Cq = *(const ulonglong2*)(qp + 8);
        ulonglong2 Dq = *(const ulonglong2*)(qp + 12);
        ulonglong2 Eq = *(const ulonglong2*)(qp + 16);
        ulonglong2 Fq = *(const ulonglong2*)(qp + 20);
        const unsigned long long q00 = Aq.x, q01 = Aq.y, q02 = Bq.x,
                                 q03 = Bq.y, q04 = Cq.x;
        const unsigned long long q10 = Dq.x, q11 = Dq.y, q12 = Eq.x,
                                 q13 = Eq.y, q14 = Fq.x;

        unsigned long long o20[5], o21[5];
        #pragma unroll
        for (int i = 0; i < 5; i++) { o20[i] = 0ull; o21[i] = 0ull; }
        float l0 = 0.0f, l1 = 0.0f;

        const float* kr = KVs + h * 980;

        #pragma unroll 1
        for (int j = 0; j < 24; j++) {
            ATT_STEP(kr);
            ATT_STEP(kr + 20);
            kr += 40;
        }
        ATT_STEP(kr);  // row 48

        {
            float inv0 = 1.0f / l0;
            unsigned long long i20 = pack2(inv0, inv0);
            float* od = Osm + r0 * 60 + h * 10;
            #pragma unroll
            for (int i = 0; i < 5; i++)
                *(unsigned long long*)(od + 2 * i) = mul2(o20[i], i20);
        }
        if (two) {
            float inv1 = 1.0f / l1;
            unsigned long long i21 = pack2(inv1, inv1);
            float* od = Osm + (r0 + 1) * 60 + h * 10;
            #pragma unroll
            for (int i = 0; i < 5; i++)
                *(unsigned long long*)(od + 2 * i) = mul2(o21[i], i21);
        }
    }
    __syncthreads();

    // ---- output projection: 7 tokens x 2 outputs, 210 threads ----
    // tg = tid/30 (broadcast Osm LDS), jg = tid%30 (coalesced LDG + STG)
    if (tid < 210) {
        const int tg = tid / 30, jg = tid % 30;
        const int t0 = tg * 7, o0 = jg * 2;
        float acc[7][2];
        #pragma unroll
        for (int j = 0; j < 2; j++) {
            float bv = __ldg(proj_b + o0 + j);
            #pragma unroll
            for (int i = 0; i < 7; i++) acc[i][j] = bv;
        }
        #pragma unroll
        for (int c4 = 0; c4 < 15; c4++) {
            float4 wv0 = __ldg(pwt + (c4)      * 30 + jg);   // j=0
            float4 wv1 = __ldg(pwt + (15 + c4) * 30 + jg);   // j=1
            #pragma unroll
            for (int i = 0; i < 7; i++) {
                float4 xv = *(const float4*)&Osm[(t0 + i) * 60 + c4 * 4];
                acc[i][0] = fmaf(xv.x, wv0.x, acc[i][0]);
                acc[i][0] = fmaf(xv.y, wv0.y, acc[i][0]);
                acc[i][0] = fmaf(xv.z, wv0.z, acc[i][0]);
                acc[i][0] = fmaf(xv.w, wv0.w, acc[i][0]);
                acc[i][1] = fmaf(xv.x, wv1.x, acc[i][1]);
                acc[i][1] = fmaf(xv.y, wv1.y, acc[i][1]);
                acc[i][1] = fmaf(xv.z, wv1.z, acc[i][1]);
                acc[i][1] = fmaf(xv.w, wv1.w, acc[i][1]);
            }
        }
        #pragma unroll
        for (int i = 0; i < 7; i++) {
            int t = t0 + i;
            int r  = wi * 7 + t / 7;
            int cc = wj * 7 + t % 7;
            if (r < 64 && cc < 64) {
                float* og4 = out + ((b * 64 + r) * 64 + cc) * 60 + o0;
                *(float2*)og4 = make_float2(acc[i][0], acc[i][1]);
            }
        }
    }
}

extern "C" void kernel_launch(void* const* d_in, const int* in_sizes, int n_in,
                              void* d_out, int out_size) {
    const float* x      = (const float*)d_in[0];
    const float* qkv_w  = (const float*)d_in[1];
    const float* qkv_b  = (const float*)d_in[2];
    const float* lscale = (const float*)d_in[3];
    const float* proj_w = (const float*)d_in[4];
    const float* proj_b = (const float*)d_in[5];
    float* out = (float*)d_out;

    transpose_weights_kernel<<<43, 256>>>(qkv_w, proj_w);

    const int smem_bytes = 12348 * 4;  // 49392 B -> 3 CTAs/SM
    cudaFuncSetAttribute(swin_win_attn_kernel,
                         cudaFuncAttributeMaxDynamicSharedMemorySize, smem_bytes);
    swin_win_attn_kernel<<<3200, 320, smem_bytes>>>(
        x, qkv_b, lscale, proj_b, out);
}